// round 3
// baseline (speedup 1.0000x reference)
#include <cuda_runtime.h>
#include <cuda_bf16.h>
#include <math_constants.h>

// Problem constants (fixed by setup_inputs)
#define NPTS  16384
#define BATCH 8
#define M     2048
#define CH    128

#define CAP       3072          // per-batch bucket capacity (mean 2048, sd ~42)
#define CHUNK_PTS 32            // points per block (8 warps x 4 points)
#define NCHUNKS   (CAP / CHUNK_PTS)   // 96

typedef unsigned long long ull;

// Device scratch (no allocs allowed)
__device__ float g_featsT[BATCH * M * CH];   // (B, m, C)
__device__ float g_ksoa[BATCH * 3 * M];      // coords SoA: [b][xyz][m]
__device__ int   g_bucket[BATCH * CAP];      // point ids grouped by batch
__device__ int   g_cnt[BATCH];               // per-batch counts

// ---------------------------------------------------------------------------
// f32x2 packed helpers (ptxas never auto-fuses these from C++)
// ---------------------------------------------------------------------------
__device__ __forceinline__ ull pack2(float lo, float hi) {
    ull r; asm("mov.b64 %0, {%1, %2};" : "=l"(r) : "f"(lo), "f"(hi)); return r;
}
__device__ __forceinline__ void unpack2(ull v, float& lo, float& hi) {
    asm("mov.b64 {%0, %1}, %2;" : "=f"(lo), "=f"(hi) : "l"(v));
}
__device__ __forceinline__ ull add2(ull a, ull b) {
    ull r; asm("add.rn.f32x2 %0, %1, %2;" : "=l"(r) : "l"(a), "l"(b)); return r;
}
__device__ __forceinline__ ull mul2(ull a, ull b) {
    ull r; asm("mul.rn.f32x2 %0, %1, %2;" : "=l"(r) : "l"(a), "l"(b)); return r;
}
__device__ __forceinline__ ull fma2(ull a, ull b, ull c) {
    ull r; asm("fma.rn.f32x2 %0, %1, %2, %3;" : "=l"(r) : "l"(a), "l"(b), "l"(c)); return r;
}

// Branchless sorted-top-3 insert: 3 FSETP + 10 SEL, no BSSY/BSYNC.
// Strict < keeps earlier (lower-index within a lane) candidate on ties.
__device__ __forceinline__ void insert3(float d, int j,
                                        float& D0, float& D1, float& D2,
                                        int& I0, int& I1, int& I2)
{
    const bool c0 = d < D0, c1 = d < D1, c2 = d < D2;
    D2 = c1 ? D1 : (c2 ? d : D2);
    I2 = c1 ? I1 : (c2 ? j : I2);
    D1 = c0 ? D0 : (c1 ? d : D1);
    I1 = c0 ? I0 : (c1 ? j : I1);
    D0 = c0 ? d  : D0;
    I0 = c0 ? j  : I0;
}

// ---------------------------------------------------------------------------
// Fused: feats transpose (B,C,m)->(B,m,C)  [z = 0..7]
//      + coord SoA split / counter zero    [z = 8]
// ---------------------------------------------------------------------------
__global__ void transpose_prep_kernel(const float* __restrict__ feats,
                                      const float* __restrict__ known)
{
    const int tx = threadIdx.x;
    const int ty = threadIdx.y;
    if (blockIdx.z < BATCH) {
        __shared__ float tile[32][33];
        const int b  = blockIdx.z;
        const int j0 = blockIdx.x * 32;   // m dimension
        const int c0 = blockIdx.y * 32;   // channel dimension
        #pragma unroll
        for (int i = ty; i < 32; i += 8)
            tile[i][tx] = feats[((size_t)(b * CH + c0 + i)) * M + j0 + tx];
        __syncthreads();
        #pragma unroll
        for (int i = ty; i < 32; i += 8)
            g_featsT[((size_t)(b * M + j0 + i)) * CH + c0 + tx] = tile[tx][i];
    } else {
        const int bid = blockIdx.x * gridDim.y + blockIdx.y;  // 0..255
        const int i = bid * 256 + ty * 32 + tx;               // 0..65535
        if (i < BATCH) g_cnt[i] = 0;
        if (i < BATCH * M) {
            const int b = i / M, j = i - b * M;
            g_ksoa[(b * 3 + 0) * M + j] = known[3 * i + 0];
            g_ksoa[(b * 3 + 1) * M + j] = known[3 * i + 1];
            g_ksoa[(b * 3 + 2) * M + j] = known[3 * i + 2];
        }
    }
}

// ---------------------------------------------------------------------------
// Bucket points by batch. Bucket ORDER is nondeterministic (atomics) but the
// output is invariant to it: each point's result depends only on its own data.
// ---------------------------------------------------------------------------
__global__ void bucket_kernel(const int* __restrict__ batch_inds)
{
    __shared__ int hist[BATCH];
    __shared__ int base[BATCH];
    __shared__ int loc[BATCH];
    const int t = threadIdx.x;
    if (t < BATCH) { hist[t] = 0; loc[t] = 0; }
    __syncthreads();

    const int p = blockIdx.x * blockDim.x + t;
    const int b = batch_inds[p];
    atomicAdd(&hist[b], 1);
    __syncthreads();

    if (t < BATCH) base[t] = atomicAdd(&g_cnt[t], hist[t]);
    __syncthreads();

    const int r   = atomicAdd(&loc[b], 1);
    const int pos = base[b] + r;
    if (pos < CAP) g_bucket[b * CAP + pos] = p;
}

// ---------------------------------------------------------------------------
// Main: block = (chunk of 32 points, batch). SoA coords in 24KB smem.
// Each warp: 4 same-batch points; each lane: 2 candidates/iter via LDS.64
// pre-packed f32x2 operands. Branchless top-3 tracking.
// ---------------------------------------------------------------------------
__global__ void __launch_bounds__(256)
knn_main_kernel(const float* __restrict__ unknown, float* __restrict__ out)
{
    __shared__ __align__(16) float sc[3 * M];     // sx | sy | sz, 24 KB
    const int b     = blockIdx.y;
    const int cnt   = g_cnt[b];
    const int start = blockIdx.x * CHUNK_PTS;
    if (start >= cnt) return;                     // uniform exit, pre-sync

    const int t = threadIdx.x;
    {
        const float4* __restrict__ src = (const float4*)(g_ksoa + b * 3 * M);
        #pragma unroll
        for (int i = t; i < 3 * M / 4; i += 256) ((float4*)sc)[i] = src[i];
    }
    __syncthreads();

    const int lane = t & 31;
    const int w    = t >> 5;

    int pid[4];
    ull nx2[4], ny2[4], nz2[4];
    #pragma unroll
    for (int k = 0; k < 4; k++) {
        const int ib = start + w * 4 + k;
        if (ib < cnt) {
            const int p = g_bucket[b * CAP + ib];
            pid[k] = p;
            const float ux = unknown[p * 3 + 0];
            const float uy = unknown[p * 3 + 1];
            const float uz = unknown[p * 3 + 2];
            nx2[k] = pack2(-ux, -ux);
            ny2[k] = pack2(-uy, -uy);
            nz2[k] = pack2(-uz, -uz);
        } else {
            pid[k] = -1;
            nx2[k] = ny2[k] = nz2[k] = 0ull;
        }
    }

    float D0[4], D1[4], D2[4];
    int   I0[4], I1[4], I2[4];
    #pragma unroll
    for (int k = 0; k < 4; k++) {
        D0[k] = D1[k] = D2[k] = CUDART_INF_F;
        I0[k] = I1[k] = I2[k] = 0;
    }

    // 32 iterations: lane handles candidate pair cp -> indices 2cp, 2cp+1
    #pragma unroll 2
    for (int it = 0; it < M / 64; it++) {
        const int cp = it * 32 + lane;
        const ull cx2 = *(const ull*)&sc[0 * M + 2 * cp];
        const ull cy2 = *(const ull*)&sc[1 * M + 2 * cp];
        const ull cz2 = *(const ull*)&sc[2 * M + 2 * cp];
        const int jA = 2 * cp;

        #pragma unroll
        for (int k = 0; k < 4; k++) {
            const ull dx2 = add2(cx2, nx2[k]);
            const ull dy2 = add2(cy2, ny2[k]);
            const ull dz2 = add2(cz2, nz2[k]);
            const ull dd  = fma2(dx2, dx2, fma2(dy2, dy2, mul2(dz2, dz2)));
            float dA, dB;
            unpack2(dd, dA, dB);
            insert3(dA, jA,     D0[k], D1[k], D2[k], I0[k], I1[k], I2[k]);
            insert3(dB, jA + 1, D0[k], D1[k], D2[k], I0[k], I1[k], I2[k]);
        }
    }

    // Per-point warp merge of top-3 (64-bit keys: d2 bits || idx, ties -> lower idx)
    #pragma unroll
    for (int k = 0; k < 4; k++) {
        const ull kl0 = ((ull)__float_as_uint(D0[k]) << 32) | (unsigned)I0[k];
        const ull kl1 = ((ull)__float_as_uint(D1[k]) << 32) | (unsigned)I1[k];
        const ull kl2 = ((ull)__float_as_uint(D2[k]) << 32) | (unsigned)I2[k];

        float wd[3]; int wi[3];
        int r = 0;
        #pragma unroll
        for (int s = 0; s < 3; s++) {
            ull v = (r == 0) ? kl0 : (r == 1) ? kl1 : (r == 2) ? kl2
                                                               : 0xFFFFFFFFFFFFFFFFull;
            const ull mine = v;
            #pragma unroll
            for (int off = 16; off; off >>= 1) {
                const ull o = __shfl_xor_sync(0xffffffffu, v, off);
                v = (o < v) ? o : v;
            }
            if (r < 3 && v == mine) r++;
            wd[s] = __uint_as_float((unsigned)(v >> 32));
            wi[s] = (int)(unsigned)(v & 0xffffffffu);
        }

        float w0 = 1.0f / (sqrtf(wd[0]) + 1e-8f);
        float w1 = 1.0f / (sqrtf(wd[1]) + 1e-8f);
        float w2 = 1.0f / (sqrtf(wd[2]) + 1e-8f);
        const float inv = 1.0f / (w0 + w1 + w2);
        w0 *= inv; w1 *= inv; w2 *= inv;

        const int bb = b;
        const float4* f0 = (const float4*)(g_featsT + ((size_t)(bb * M + wi[0])) * CH);
        const float4* f1 = (const float4*)(g_featsT + ((size_t)(bb * M + wi[1])) * CH);
        const float4* f2 = (const float4*)(g_featsT + ((size_t)(bb * M + wi[2])) * CH);

        const float4 a0 = f0[lane], a1 = f1[lane], a2 = f2[lane];
        float4 o;
        o.x = fmaf(w0, a0.x, fmaf(w1, a1.x, w2 * a2.x));
        o.y = fmaf(w0, a0.y, fmaf(w1, a1.y, w2 * a2.y));
        o.z = fmaf(w0, a0.z, fmaf(w1, a1.z, w2 * a2.z));
        o.w = fmaf(w0, a0.w, fmaf(w1, a1.w, w2 * a2.w));

        if (pid[k] >= 0)
            ((float4*)out)[(size_t)pid[k] * (CH / 4) + lane] = o;
    }
}

// ---------------------------------------------------------------------------
extern "C" void kernel_launch(void* const* d_in, const int* in_sizes, int n_in,
                              void* d_out, int out_size)
{
    const float* unknown     = (const float*)d_in[0];
    const float* known       = (const float*)d_in[1];
    const int*   batch_inds  = (const int*)d_in[2];
    const float* known_feats = (const float*)d_in[3];
    float* out = (float*)d_out;

    transpose_prep_kernel<<<dim3(M / 32, CH / 32, BATCH + 1), dim3(32, 8)>>>(known_feats, unknown /*unused*/ == nullptr ? nullptr : known);
    bucket_kernel<<<NPTS / 256, 256>>>(batch_inds);
    knn_main_kernel<<<dim3(NCHUNKS, BATCH), 256>>>(unknown, out);
}

// round 4
// speedup vs baseline: 1.2758x; 1.2758x over previous
#include <cuda_runtime.h>
#include <cuda_bf16.h>
#include <math_constants.h>

// Problem constants (fixed by setup_inputs)
#define NPTS  16384
#define BATCH 8
#define M     2048
#define CH    128

#define CAP       3072               // per-batch bucket capacity (mean 2048, sd ~42)
#define CHUNK_PTS 16                 // points per block (8 warps x 2 points)
#define NCHUNKS   (CAP / CHUNK_PTS)  // 192

typedef unsigned long long ull;

// Device scratch (no allocs allowed)
__device__ float  g_featsT[BATCH * M * CH];   // (B, m, C)
__device__ float4 g_known4[BATCH * M];        // coords padded to float4
__device__ int    g_bucket[BATCH * CAP];      // point ids grouped by batch
__device__ int    g_cnt[BATCH];               // per-batch counts

// Branchless sorted-top-3 insert: 3 FSETP + 10 SEL, no BSSY/BSYNC.
// Strict < keeps the earlier (lower-index within a lane) candidate on ties.
__device__ __forceinline__ void insert3(float d, int j,
                                        float& D0, float& D1, float& D2,
                                        int& I0, int& I1, int& I2)
{
    const bool c0 = d < D0, c1 = d < D1, c2 = d < D2;
    D2 = c1 ? D1 : (c2 ? d : D2);
    I2 = c1 ? I1 : (c2 ? j : I2);
    D1 = c0 ? D0 : (c1 ? d : D1);
    I1 = c0 ? I0 : (c1 ? j : I1);
    D0 = c0 ? d  : D0;
    I0 = c0 ? j  : I0;
}

// ---------------------------------------------------------------------------
// Fused: feats transpose (B,C,m)->(B,m,C) with float4 both sides [z = 0..7]
//      + coord float4 pack / counter zero                        [z = 8]
// Block tile: 32 channels x 128 m. Threads (32,8).
// ---------------------------------------------------------------------------
__global__ void transpose_prep_kernel(const float* __restrict__ feats,
                                      const float* __restrict__ known)
{
    const int tx = threadIdx.x;
    const int ty = threadIdx.y;
    const int t  = ty * 32 + tx;

    if (blockIdx.z < BATCH) {
        __shared__ float tile[32][132];    // row stride 132 floats (528B, 16B-aligned)
        const int b  = blockIdx.z;
        const int j0 = blockIdx.x * 128;   // m tile
        const int c0 = blockIdx.y * 32;    // channel tile

        // load: 4 float4 per thread, coalesced along m
        #pragma unroll
        for (int i = 0; i < 4; i++) {
            const int c = ty + i * 8;
            const float4 v = *(const float4*)&feats[((size_t)(b * CH + c0 + c)) * M + j0 + tx * 4];
            *(float4*)&tile[c][tx * 4] = v;
        }
        __syncthreads();

        // store: 4 float4 per thread, coalesced along C
        #pragma unroll
        for (int s = 0; s < 4; s++) {
            const int e = t + 256 * s;     // 0..1023
            const int j = e >> 3;          // 0..127
            const int q = e & 7;           // float4 chunk within 32 channels
            float4 v;
            v.x = tile[4 * q + 0][j];
            v.y = tile[4 * q + 1][j];
            v.z = tile[4 * q + 2][j];
            v.w = tile[4 * q + 3][j];
            *(float4*)&g_featsT[((size_t)(b * M + j0 + j)) * CH + c0 + 4 * q] = v;
        }
    } else {
        const int i = (blockIdx.x * gridDim.y + blockIdx.y) * 256 + t;  // 0..16383
        if (i < BATCH) g_cnt[i] = 0;
        if (i < BATCH * M) {
            const float x = known[3 * i + 0];
            const float y = known[3 * i + 1];
            const float z = known[3 * i + 2];
            g_known4[i] = make_float4(x, y, z, 0.0f);
        }
    }
}

// ---------------------------------------------------------------------------
// Bucket points by batch. Bucket ORDER is nondeterministic (atomics) but the
// output is invariant to it: each point's result depends only on its own data.
// ---------------------------------------------------------------------------
__global__ void bucket_kernel(const int* __restrict__ batch_inds)
{
    __shared__ int hist[BATCH];
    __shared__ int base[BATCH];
    __shared__ int loc[BATCH];
    const int t = threadIdx.x;
    if (t < BATCH) { hist[t] = 0; loc[t] = 0; }
    __syncthreads();

    const int p = blockIdx.x * blockDim.x + t;
    const int b = batch_inds[p];
    atomicAdd(&hist[b], 1);
    __syncthreads();

    if (t < BATCH) base[t] = atomicAdd(&g_cnt[t], hist[t]);
    __syncthreads();

    const int r   = atomicAdd(&loc[b], 1);
    const int pos = base[b] + r;
    if (pos < CAP) g_bucket[b * CAP + pos] = p;
}

// ---------------------------------------------------------------------------
// Main: block = (chunk of 16 points, batch). One batch's 2048 coords (float4)
// in 32KB smem. Each warp: 2 same-batch points; lanes stride the candidates;
// branchless top-3 tracking (plain fp32 math, exact reference rounding).
// ---------------------------------------------------------------------------
__global__ void __launch_bounds__(256)
knn_main_kernel(const float* __restrict__ unknown, float* __restrict__ out)
{
    __shared__ float4 sc[M];                      // 32 KB
    const int b     = blockIdx.y;
    const int cnt   = g_cnt[b];
    const int start = blockIdx.x * CHUNK_PTS;
    if (start >= cnt) return;                     // uniform exit, pre-sync

    const int t = threadIdx.x;
    {
        const float4* __restrict__ src = g_known4 + b * M;
        #pragma unroll
        for (int i = 0; i < M / 256; i++) sc[t + 256 * i] = src[t + 256 * i];
    }
    __syncthreads();

    const int lane = t & 31;
    const int w    = t >> 5;

    int   pid[2];
    float ux[2], uy[2], uz[2];
    #pragma unroll
    for (int k = 0; k < 2; k++) {
        const int ib = start + w * 2 + k;
        if (ib < cnt) {
            const int p = g_bucket[b * CAP + ib];
            pid[k] = p;
            ux[k] = unknown[p * 3 + 0];
            uy[k] = unknown[p * 3 + 1];
            uz[k] = unknown[p * 3 + 2];
        } else {
            pid[k] = -1;
            ux[k] = uy[k] = uz[k] = 0.0f;
        }
    }

    float D0[2], D1[2], D2[2];
    int   I0[2], I1[2], I2[2];
    #pragma unroll
    for (int k = 0; k < 2; k++) {
        D0[k] = D1[k] = D2[k] = CUDART_INF_F;
        I0[k] = I1[k] = I2[k] = 0;
    }

    #pragma unroll 4
    for (int it = 0; it < M / 32; it++) {
        const int j = it * 32 + lane;
        const float4 c = sc[j];
        #pragma unroll
        for (int k = 0; k < 2; k++) {
            const float dx = c.x - ux[k];
            const float dy = c.y - uy[k];
            const float dz = c.z - uz[k];
            const float d  = fmaf(dx, dx, fmaf(dy, dy, dz * dz));
            insert3(d, j, D0[k], D1[k], D2[k], I0[k], I1[k], I2[k]);
        }
    }

    // Per-point warp merge of top-3 (64-bit keys: d bits || idx, ties -> lower idx)
    #pragma unroll
    for (int k = 0; k < 2; k++) {
        const ull kl0 = ((ull)__float_as_uint(D0[k]) << 32) | (unsigned)I0[k];
        const ull kl1 = ((ull)__float_as_uint(D1[k]) << 32) | (unsigned)I1[k];
        const ull kl2 = ((ull)__float_as_uint(D2[k]) << 32) | (unsigned)I2[k];

        float wd[3]; int wi[3];
        int r = 0;
        #pragma unroll
        for (int s = 0; s < 3; s++) {
            ull v = (r == 0) ? kl0 : (r == 1) ? kl1 : (r == 2) ? kl2
                                                               : 0xFFFFFFFFFFFFFFFFull;
            const ull mine = v;
            #pragma unroll
            for (int off = 16; off; off >>= 1) {
                const ull o = __shfl_xor_sync(0xffffffffu, v, off);
                v = (o < v) ? o : v;
            }
            if (r < 3 && v == mine) r++;
            wd[s] = __uint_as_float((unsigned)(v >> 32));
            wi[s] = (int)(unsigned)(v & 0xffffffffu);
        }

        float w0 = 1.0f / (sqrtf(wd[0]) + 1e-8f);
        float w1 = 1.0f / (sqrtf(wd[1]) + 1e-8f);
        float w2 = 1.0f / (sqrtf(wd[2]) + 1e-8f);
        const float inv = 1.0f / (w0 + w1 + w2);
        w0 *= inv; w1 *= inv; w2 *= inv;

        const float4* f0 = (const float4*)(g_featsT + ((size_t)(b * M + wi[0])) * CH);
        const float4* f1 = (const float4*)(g_featsT + ((size_t)(b * M + wi[1])) * CH);
        const float4* f2 = (const float4*)(g_featsT + ((size_t)(b * M + wi[2])) * CH);

        const float4 a0 = f0[lane], a1 = f1[lane], a2 = f2[lane];
        float4 o;
        o.x = fmaf(w0, a0.x, fmaf(w1, a1.x, w2 * a2.x));
        o.y = fmaf(w0, a0.y, fmaf(w1, a1.y, w2 * a2.y));
        o.z = fmaf(w0, a0.z, fmaf(w1, a1.z, w2 * a2.z));
        o.w = fmaf(w0, a0.w, fmaf(w1, a1.w, w2 * a2.w));

        if (pid[k] >= 0)
            ((float4*)out)[(size_t)pid[k] * (CH / 4) + lane] = o;
    }
}

// ---------------------------------------------------------------------------
extern "C" void kernel_launch(void* const* d_in, const int* in_sizes, int n_in,
                              void* d_out, int out_size)
{
    const float* unknown     = (const float*)d_in[0];
    const float* known       = (const float*)d_in[1];
    const int*   batch_inds  = (const int*)d_in[2];
    const float* known_feats = (const float*)d_in[3];
    float* out = (float*)d_out;

    transpose_prep_kernel<<<dim3(M / 128, CH / 32, BATCH + 1), dim3(32, 8)>>>(known_feats, known);
    bucket_kernel<<<NPTS / 256, 256>>>(batch_inds);
    knn_main_kernel<<<dim3(NCHUNKS, BATCH), 256>>>(unknown, out);
}

// round 5
// speedup vs baseline: 1.5383x; 1.2058x over previous
#include <cuda_runtime.h>
#include <cuda_bf16.h>
#include <math_constants.h>

// Problem constants (fixed by setup_inputs)
#define NPTS  16384
#define BATCH 8
#define M     2048
#define CH    128

#define CAP       3072               // per-batch bucket capacity (mean 2048, sd ~42)
#define CHUNK_PTS 16                 // points per block (8 warps x 2 points)
#define NCHUNKS   (CAP / CHUNK_PTS)  // 192
#define FULL 0xffffffffu

typedef unsigned long long ull;

// Device scratch (no allocs allowed)
__device__ float  g_featsT[BATCH * M * CH];   // (B, m, C)
__device__ float4 g_known4[BATCH * M];        // coords padded to float4
__device__ int    g_bucket[BATCH * CAP];      // point ids grouped by batch
__device__ int    g_cnt[BATCH];               // per-batch counts

// ---------------------------------------------------------------------------
// Fused: feats transpose (B,C,m)->(B,m,C), 32x32 tiles, XOR-swizzled smem
// (conflict-free load and store phases)            [z = 0..7]
//      + coord float4 pack / counter zero          [z = 8]
// Block: 256 threads flat.
// ---------------------------------------------------------------------------
__global__ void __launch_bounds__(256)
transpose_prep_kernel(const float* __restrict__ feats,
                      const float* __restrict__ known)
{
    const int t = threadIdx.x;
    if (blockIdx.z < BATCH) {
        __shared__ float4 tile4[32 * 8];      // 4KB, element (c,j) at
                                              // tile4[c*8 + ((j>>2) ^ (c>>2))].comp(j&3)
        const int b  = blockIdx.z;
        const int j0 = blockIdx.x * 32;       // m tile
        const int c0 = blockIdx.y * 32;       // channel tile

        {   // load: thread t -> channel c = t>>3, float4-chunk m4 = t&7 (coalesced on m)
            const int c  = t >> 3;
            const int m4 = t & 7;
            const float4 v = *(const float4*)&feats[((size_t)(b * CH + c0 + c)) * M + j0 + m4 * 4];
            tile4[c * 8 + (m4 ^ ((c >> 2) & 7))] = v;
        }
        __syncthreads();
        {   // store: thread t -> m row j = t>>3, channel-chunk q = t&7 (coalesced on C)
            const int j = t >> 3;
            const int q = t & 7;
            const float* tf   = (const float*)tile4;
            const int    col4 = j >> 2;
            const int    comp = j & 3;
            float vv[4];
            #pragma unroll
            for (int i = 0; i < 4; i++) {
                const int c = 4 * q + i;
                vv[i] = tf[c * 32 + ((col4 ^ ((c >> 2) & 7)) * 4) + comp];
            }
            *(float4*)&g_featsT[((size_t)(b * M + j0 + j)) * CH + c0 + 4 * q] =
                make_float4(vv[0], vv[1], vv[2], vv[3]);
        }
    } else {
        const int i = (blockIdx.x * gridDim.y + blockIdx.y) * 256 + t;  // 0..65535
        if (i < BATCH) g_cnt[i] = 0;
        if (i < BATCH * M) {
            const float x = known[3 * i + 0];
            const float y = known[3 * i + 1];
            const float z = known[3 * i + 2];
            g_known4[i] = make_float4(x, y, z, 0.0f);
        }
    }
}

// ---------------------------------------------------------------------------
// Bucket points by batch. Bucket ORDER is nondeterministic (atomics) but the
// output is invariant to it: each point's result depends only on its own data.
// ---------------------------------------------------------------------------
__global__ void bucket_kernel(const int* __restrict__ batch_inds)
{
    __shared__ int hist[BATCH];
    __shared__ int base[BATCH];
    __shared__ int loc[BATCH];
    const int t = threadIdx.x;
    if (t < BATCH) { hist[t] = 0; loc[t] = 0; }
    __syncthreads();

    const int p = blockIdx.x * blockDim.x + t;
    const int b = batch_inds[p];
    atomicAdd(&hist[b], 1);
    __syncthreads();

    if (t < BATCH) base[t] = atomicAdd(&g_cnt[t], hist[t]);
    __syncthreads();

    const int r   = atomicAdd(&loc[b], 1);
    const int pos = base[b] + r;
    if (pos < CAP) g_bucket[b * CAP + pos] = p;
}

// ---------------------------------------------------------------------------
// Warp-collective top-3 update, called only on triggering batches (warp-
// uniform entry). Keys are (d_bits << 32 | idx): uint order of non-negative
// floats is monotone, ties resolve to the lower index (jax top_k semantics).
// k0<=k1<=k2 are replicated across the warp.
// ---------------------------------------------------------------------------
__device__ __forceinline__ void topk_update(bool pass, float d, int base, int lane,
                                            ull& k0, ull& k1, ull& k2)
{
    unsigned cur = pass ? __float_as_uint(d) : 0xFFFFFFFFu;
    while (true) {
        const unsigned mind   = __reduce_min_sync(FULL, cur);
        const unsigned owners = __ballot_sync(FULL, cur == mind);
        const int      src    = __ffs(owners) - 1;      // lowest lane = lowest idx
        const ull      mkey   = ((ull)mind << 32) | (unsigned)(base + src);
        if (mkey >= k2) break;
        const bool b0 = mkey < k0, b1 = mkey < k1;
        k2 = b1 ? k1 : mkey;
        k1 = b0 ? k0 : (b1 ? mkey : k1);
        k0 = b0 ? mkey : k0;
        if (lane == src) cur = 0xFFFFFFFFu;             // consume winner
        if (!__any_sync(FULL, cur <= (unsigned)(k2 >> 32))) break;  // cheap pre-break
    }
}

// Weights + feature gather + output write for one finished point.
__device__ __forceinline__ void write_point(int pid, int b, ull k0, ull k1, ull k2,
                                            int lane, float* __restrict__ out)
{
    const float d0 = __uint_as_float((unsigned)(k0 >> 32));
    const float d1 = __uint_as_float((unsigned)(k1 >> 32));
    const float d2 = __uint_as_float((unsigned)(k2 >> 32));
    float w0 = 1.0f / (sqrtf(d0) + 1e-8f);
    float w1 = 1.0f / (sqrtf(d1) + 1e-8f);
    float w2 = 1.0f / (sqrtf(d2) + 1e-8f);
    const float inv = 1.0f / (w0 + w1 + w2);
    w0 *= inv; w1 *= inv; w2 *= inv;

    const int i0 = (int)(unsigned)k0;
    const int i1 = (int)(unsigned)k1;
    const int i2 = (int)(unsigned)k2;

    const float4 a0 = ((const float4*)(g_featsT + ((size_t)(b * M + i0)) * CH))[lane];
    const float4 a1 = ((const float4*)(g_featsT + ((size_t)(b * M + i1)) * CH))[lane];
    const float4 a2 = ((const float4*)(g_featsT + ((size_t)(b * M + i2)) * CH))[lane];
    float4 o;
    o.x = fmaf(w0, a0.x, fmaf(w1, a1.x, w2 * a2.x));
    o.y = fmaf(w0, a0.y, fmaf(w1, a1.y, w2 * a2.y));
    o.z = fmaf(w0, a0.z, fmaf(w1, a1.z, w2 * a2.z));
    o.w = fmaf(w0, a0.w, fmaf(w1, a1.w, w2 * a2.w));
    ((float4*)out)[(size_t)pid * (CH / 4) + lane] = o;
}

// ---------------------------------------------------------------------------
// Main: block = (chunk of 16 points, batch). One batch's 2048 coords (float4)
// in 32KB smem. Each warp: 2 same-batch points. Fast path per 32-candidate
// batch: distances + threshold test + one warp vote; warp-collective top-3
// update only on triggering batches.
// ---------------------------------------------------------------------------
__global__ void __launch_bounds__(256)
knn_main_kernel(const float* __restrict__ unknown, float* __restrict__ out)
{
    __shared__ float4 sc[M];                      // 32 KB
    const int b     = blockIdx.y;
    const int cnt   = g_cnt[b];
    const int start = blockIdx.x * CHUNK_PTS;
    if (start >= cnt) return;                     // uniform exit, pre-sync

    const int t = threadIdx.x;
    {
        const float4* __restrict__ src4 = g_known4 + b * M;
        #pragma unroll
        for (int i = 0; i < M / 256; i++) sc[t + 256 * i] = src4[t + 256 * i];
    }
    __syncthreads();

    const int lane = t & 31;
    const int w    = t >> 5;

    int   pidA = -1, pidB = -1;
    float uxA = 0.f, uyA = 0.f, uzA = 0.f;
    float uxB = 0.f, uyB = 0.f, uzB = 0.f;
    float t2A = -CUDART_INF_F, t2B = -CUDART_INF_F;   // inactive -> never passes

    const int ibA = start + w * 2;
    const int ibB = ibA + 1;
    if (ibA < cnt) {
        pidA = g_bucket[b * CAP + ibA];
        uxA = unknown[pidA * 3 + 0];
        uyA = unknown[pidA * 3 + 1];
        uzA = unknown[pidA * 3 + 2];
        t2A = CUDART_INF_F;
    }
    if (ibB < cnt) {
        pidB = g_bucket[b * CAP + ibB];
        uxB = unknown[pidB * 3 + 0];
        uyB = unknown[pidB * 3 + 1];
        uzB = unknown[pidB * 3 + 2];
        t2B = CUDART_INF_F;
    }

    ull k0A = ~0ull, k1A = ~0ull, k2A = ~0ull;
    ull k0B = ~0ull, k1B = ~0ull, k2B = ~0ull;

    #pragma unroll 2
    for (int it = 0; it < M / 32; it++) {
        const int base = it * 32;
        const float4 c = sc[base + lane];

        const float dxA = c.x - uxA, dyA = c.y - uyA, dzA = c.z - uzA;
        const float dA  = fmaf(dxA, dxA, fmaf(dyA, dyA, dzA * dzA));
        const float dxB = c.x - uxB, dyB = c.y - uyB, dzB = c.z - uzB;
        const float dB  = fmaf(dxB, dxB, fmaf(dyB, dyB, dzB * dzB));

        const bool pA = dA <= t2A;   // <= catches exact ties; key guard resolves index order
        const bool pB = dB <= t2B;
        if (__any_sync(FULL, pA || pB)) {
            if (__any_sync(FULL, pA)) {
                topk_update(pA, dA, base, lane, k0A, k1A, k2A);
                t2A = __uint_as_float((unsigned)(k2A >> 32));
            }
            if (__any_sync(FULL, pB)) {
                topk_update(pB, dB, base, lane, k0B, k1B, k2B);
                t2B = __uint_as_float((unsigned)(k2B >> 32));
            }
        }
    }

    if (pidA >= 0) write_point(pidA, b, k0A, k1A, k2A, lane, out);
    if (pidB >= 0) write_point(pidB, b, k0B, k1B, k2B, lane, out);
}

// ---------------------------------------------------------------------------
extern "C" void kernel_launch(void* const* d_in, const int* in_sizes, int n_in,
                              void* d_out, int out_size)
{
    const float* unknown     = (const float*)d_in[0];
    const float* known       = (const float*)d_in[1];
    const int*   batch_inds  = (const int*)d_in[2];
    const float* known_feats = (const float*)d_in[3];
    float* out = (float*)d_out;

    transpose_prep_kernel<<<dim3(M / 32, CH / 32, BATCH + 1), 256>>>(known_feats, known);
    bucket_kernel<<<NPTS / 256, 256>>>(batch_inds);
    knn_main_kernel<<<dim3(NCHUNKS, BATCH), 256>>>(unknown, out);
}